// round 15
// baseline (speedup 1.0000x reference)
#include <cuda_runtime.h>
#include <cstdint>

#define B 8
#define N 32768
#define K 1024
#define C 128
#define CSIZE 16                 // CTAs per cluster (one cluster per batch)
#define T 160                    // 4 FPS warps + 1 gather warp
#define TF 128                   // FPS threads per CTA
#define NW 4                     // FPS warps per CTA
#define PPT 16                   // points per thread
#define NPAIR 8                  // f32x2 pairs per thread
#define SLOTS (CSIZE * NW)       // 64 warp-winner slots per CTA
#define TXK (SLOTS * 8)          // key barrier: 64 x 1 st.async.b64 = 512 B
#define TXC (SLOTS * 16)         // coord barrier: 64 x 2 st.async.b64 = 1024 B
#define FULL 0xffffffffu

typedef unsigned long long u64;

// ---------------- PTX helpers ----------------
__device__ __forceinline__ unsigned smem_u32(const void* p) {
    return (unsigned)__cvta_generic_to_shared(p);
}
__device__ __forceinline__ unsigned mapa_u32(unsigned addr, unsigned rank) {
    unsigned r;
    asm("mapa.shared::cluster.u32 %0, %1, %2;" : "=r"(r) : "r"(addr), "r"(rank));
    return r;
}
__device__ __forceinline__ u64 pk2f(float lo, float hi) {
    u64 v; asm("mov.b64 %0, {%1, %2};" : "=l"(v) : "f"(lo), "f"(hi)); return v;
}
__device__ __forceinline__ void upk2f(float& lo, float& hi, u64 v) {
    asm("mov.b64 {%0, %1}, %2;" : "=f"(lo), "=f"(hi) : "l"(v));
}
__device__ __forceinline__ u64 addx2(u64 a, u64 b) {
    u64 r; asm("add.rn.f32x2 %0, %1, %2;" : "=l"(r) : "l"(a), "l"(b)); return r;
}
__device__ __forceinline__ u64 subx2(u64 a, u64 b) {
    u64 r; asm("sub.rn.f32x2 %0, %1, %2;" : "=l"(r) : "l"(a), "l"(b)); return r;
}
__device__ __forceinline__ u64 mulx2(u64 a, u64 b) {
    u64 r; asm("mul.rn.f32x2 %0, %1, %2;" : "=l"(r) : "l"(a), "l"(b)); return r;
}
__device__ __forceinline__ void mbar_init(unsigned bar, unsigned cnt) {
    asm volatile("mbarrier.init.shared.b64 [%0], %1;" :: "r"(bar), "r"(cnt) : "memory");
}
// arrive(1) + raise expected tx: standard per-phase arming
__device__ __forceinline__ void mbar_expect(unsigned bar, unsigned tx) {
    asm volatile("mbarrier.arrive.expect_tx.shared.b64 _, [%0], %1;"
                 :: "r"(bar), "r"(tx) : "memory");
}
__device__ __forceinline__ void st_async64(unsigned raddr, u64 v, unsigned rbar) {
    asm volatile(
        "st.async.shared::cluster.mbarrier::complete_tx::bytes.b64 [%0], %1, [%2];"
        :: "r"(raddr), "l"(v), "r"(rbar) : "memory");
}
__device__ __forceinline__ void mbar_wait(unsigned bar, unsigned ph) {
    asm volatile(
        "{\n\t"
        ".reg .pred P;\n\t"
        "WL_%=:\n\t"
        "mbarrier.try_wait.parity.acquire.cluster.shared::cta.b64 P, [%0], %1, 0x989680;\n\t"
        "@P bra WD_%=;\n\t"
        "bra WL_%=;\n\t"
        "WD_%=:\n\t"
        "}"
        :: "r"(bar), "r"(ph) : "memory");
}
__device__ __forceinline__ u64 ld_smem64(unsigned addr) {
    u64 v;
    asm volatile("ld.shared.b64 %0, [%1];" : "=l"(v) : "r"(addr) : "memory");
    return v;
}
__device__ __forceinline__ void cluster_sync_all() {
    asm volatile("barrier.cluster.arrive.aligned;" ::: "memory");
    asm volatile("barrier.cluster.wait.aligned;" ::: "memory");
}
// 8-way u64 select by 3-bit p
__device__ __forceinline__ u64 sel8(const u64* A, int p) {
    u64 a0 = (p & 1) ? A[1] : A[0];
    u64 a1 = (p & 1) ? A[3] : A[2];
    u64 a2 = (p & 1) ? A[5] : A[4];
    u64 a3 = (p & 1) ? A[7] : A[6];
    u64 b0 = (p & 2) ? a1 : a0;
    u64 b1 = (p & 2) ? a3 : a2;
    return (p & 4) ? b1 : b0;
}

__global__ void __launch_bounds__(T, 1)
fps_kernel(const float* __restrict__ xyz, const float* __restrict__ feat,
           float* __restrict__ out) {
    // double-buffered exchange: packed (d,~idx) keys + coords
    __shared__ u64 s_di[2][SLOTS];   // (d<<32) | (~idx & 0x7fff)
    __shared__ u64 s_xy[2][SLOTS];   // packed (x, y)
    __shared__ u64 s_z[2][SLOTS];    // z bits in low 32
    __shared__ u64 s_kbar[2];        // key barriers  (gate the scan)
    __shared__ u64 s_cbar[2];        // coord barriers (waited after the scan)
    __shared__ int s_idx[K];         // published sample indices (-1 = not yet)

    const int t = threadIdx.x;
    const int lane = t & 31;
    const int w = t >> 5;
    const int blk = blockIdx.x;
    const int b = blk / CSIZE;       // batch (clusters contiguous in x)
    const int r = blk % CSIZE;       // cluster rank

    const float* xb = xyz + (size_t)b * 3 * N;
    const float* fb = feat + (size_t)b * C * N;

    // publish buffer init: -1 everywhere, sample 0 is index 0
    for (int i = t; i < K; i += T) s_idx[i] = -1;
    if (t == 0) s_idx[0] = 0;

    const unsigned kbar0 = smem_u32(&s_kbar[0]);
    const unsigned kbar1 = smem_u32(&s_kbar[1]);
    const unsigned cbar0 = smem_u32(&s_cbar[0]);
    const unsigned cbar1 = smem_u32(&s_cbar[1]);
    if (t == 0) {
        mbar_init(kbar0, 1); mbar_init(kbar1, 1);
        mbar_init(cbar0, 1); mbar_init(cbar1, 1);
    }
    __syncthreads();
    // Arm all first phases BEFORE any remote can complete_tx
    if (t == 0) {
        mbar_expect(kbar0, TXK); mbar_expect(kbar1, TXK);
        mbar_expect(cbar0, TXC); mbar_expect(cbar1, TXC);
    }
    cluster_sync_all();

    if (w < NW) {
        // ================= FPS warps (r9 loop verbatim) =================
        u64 PX[NPAIR], PY[NPAIR], PZ[NPAIR];
        float pd[PPT];
        const int base = r * (N / CSIZE) + t;
#pragma unroll
        for (int p = 0; p < NPAIR; p++) {
            PX[p] = pk2f(xb[base + (2 * p) * TF],         xb[base + (2 * p + 1) * TF]);
            PY[p] = pk2f(xb[N + base + (2 * p) * TF],     xb[N + base + (2 * p + 1) * TF]);
            PZ[p] = pk2f(xb[2 * N + base + (2 * p) * TF], xb[2 * N + base + (2 * p + 1) * TF]);
        }
#pragma unroll
        for (int j = 0; j < PPT; j++) pd[j] = __int_as_float(0x7f800000);  // +inf

        // Hoisted DSMEM destination addresses. Rotation spreads fabric load.
        unsigned ra_di[2], ra_xy[2], ra_z[2], rkb[2], rcb[2];
        {
            const int slot = r * NW + w;
            const unsigned q = (unsigned)((lane + r) & 15);
            ra_di[0] = mapa_u32(smem_u32(&s_di[0][slot]), q);
            ra_di[1] = mapa_u32(smem_u32(&s_di[1][slot]), q);
            ra_xy[0] = mapa_u32(smem_u32(&s_xy[0][slot]), q);
            ra_xy[1] = mapa_u32(smem_u32(&s_xy[1][slot]), q);
            ra_z[0]  = mapa_u32(smem_u32(&s_z[0][slot]),  q);
            ra_z[1]  = mapa_u32(smem_u32(&s_z[1][slot]),  q);
            rkb[0]   = mapa_u32(kbar0, q);
            rkb[1]   = mapa_u32(kbar1, q);
            rcb[0]   = mapa_u32(cbar0, q);
            rcb[1]   = mapa_u32(cbar1, q);
        }
        const unsigned pa0[2] = { smem_u32(&s_di[0][lane]), smem_u32(&s_di[1][lane]) };
        const unsigned pa1[2] = { smem_u32(&s_di[0][lane + 32]), smem_u32(&s_di[1][lane + 32]) };

        int cur = 0;
        float cx = xb[0], cy = xb[N], cz = xb[2 * N];

        for (int s = 0; s < K; s++) {
            // ---- packed distance update + thread-local argmax ----
            const u64 ccx = pk2f(cx, cx);
            const u64 ccy = pk2f(cy, cy);
            const u64 ccz = pk2f(cz, cz);
            unsigned bestd = 0; int bestj = 0;
#pragma unroll
            for (int p = 0; p < NPAIR; p++) {
                u64 dx = subx2(PX[p], ccx);
                u64 dy = subx2(PY[p], ccy);
                u64 dz = subx2(PZ[p], ccz);
                u64 d2 = addx2(addx2(mulx2(dx, dx), mulx2(dy, dy)), mulx2(dz, dz));
                float da, db; upk2f(da, db, d2);
                float n0 = fminf(pd[2 * p], da);     pd[2 * p] = n0;
                unsigned u0 = __float_as_uint(n0);
                if (u0 > bestd) { bestd = u0; bestj = 2 * p; }   // strict > -> min idx
                float n1 = fminf(pd[2 * p + 1], db); pd[2 * p + 1] = n1;
                unsigned u1 = __float_as_uint(n1);
                if (u1 > bestd) { bestd = u1; bestj = 2 * p + 1; }
            }
            const unsigned besti = (unsigned)(base + (bestj << 7));   // bestj * TF

            // ---- warp reduce: max dist, tie-break min idx ----
            const unsigned wm = __reduce_max_sync(FULL, bestd);
            const unsigned cand = (bestd == wm) ? ((besti << 5) | (unsigned)lane) : FULL;
            const unsigned cm = __reduce_min_sync(FULL, cand);
            const int sr = (int)(cm & 31);
            const unsigned wi = cm >> 5;

            const int par = s & 1;
            const unsigned ph = (unsigned)((s >> 1) & 1);
            const unsigned kbarp = par ? kbar1 : kbar0;
            const unsigned cbarp = par ? cbar1 : cbar0;

            // ---- send packed key IMMEDIATELY (completes on KEY barrier) ----
            if (lane < CSIZE) {
                const u64 key = ((u64)wm << 32) | (u64)((wi ^ 0x7fffu) & 0x7fffu);
                st_async64(ra_di[par], key, rkb[par]);
            }

            // ---- coords resolved + broadcast + sent (COORD barrier) ----
            {
                const int pp = bestj >> 1;
                float xl, xh, yl, yh, zl, zh;
                upk2f(xl, xh, sel8(PX, pp));
                upk2f(yl, yh, sel8(PY, pp));
                upk2f(zl, zh, sel8(PZ, pp));
                const bool hi = bestj & 1;
                float bx = hi ? xh : xl;
                float by = hi ? yh : yl;
                float bz = hi ? zh : zl;
                bx = __shfl_sync(FULL, bx, sr);
                by = __shfl_sync(FULL, by, sr);
                bz = __shfl_sync(FULL, bz, sr);
                if (lane < CSIZE) {
                    st_async64(ra_xy[par], pk2f(bx, by), rcb[par]);
                    st_async64(ra_z[par],  (u64)__float_as_uint(bz), rcb[par]);
                }
            }

            // ---- wait KEYS only; re-arm for s+2 ----
            mbar_wait(kbarp, ph);
            if (t == 0) mbar_expect(kbarp, TXK);

            // ---- warp-cooperative global winner over 64 packed keys ----
            const u64 k0 = ld_smem64(pa0[par]);
            const u64 k1 = ld_smem64(pa1[par]);
            const bool take1 = k1 > k0;          // (max d, min idx) in one compare
            const u64 km = take1 ? k1 : k0;
            const unsigned dl = (unsigned)(km >> 32);
            const unsigned lo15 = (unsigned)km & 0x7fffu;    // ~idx
            const unsigned sl = (unsigned)lane + (take1 ? 32u : 0u);

            const unsigned gm = __reduce_max_sync(FULL, dl);
            const unsigned c2 = (dl == gm) ? ((lo15 << 6) | sl) : 0u;
            const unsigned cm2 = __reduce_max_sync(FULL, c2);  // max ~idx = min idx
            const int slotw = (int)(cm2 & 63);
            cur = (int)(((cm2 >> 6) ^ 0x7fffu) & 0x7fffu);

            // ---- now wait coords (usually already complete -> fast path) ----
            mbar_wait(cbarp, ph);
            if (t == 0) mbar_expect(cbarp, TXC);

            float fx, fy;
            upk2f(fx, fy, ld_smem64(smem_u32(&s_xy[par][slotw])));
            cx = fx; cy = fy;
            cz = __uint_as_float((unsigned)ld_smem64(smem_u32(&s_z[par][slotw])));

            // publish sample s+1 (t127: not a sender lane 0-15 re-armer; shadowed)
            if (t == TF - 1 && s + 1 < K) *(volatile int*)&s_idx[s + 1] = cur;
        }
    } else {
        // ================= gather warp (concurrent, off critical path) ===
        // This CTA owns channels e = r, r+16, ... (<131). Lane l -> channel r+16l.
        const int e = r + 16 * lane;
        const bool act = (e < 3 + C);
        const float* src = 0;
        float* dst = 0;
        if (act) {
            if (e < 3) {
                src = xb + (size_t)e * N;
                dst = out + ((size_t)(b * 3 + e)) * K;
            } else {
                src = fb + (size_t)(e - 3) * N;
                dst = out + (size_t)B * 3 * K + ((size_t)(b * C + (e - 3))) * K;
            }
        }
        for (int s = 0; s < K; s++) {
            int id;
            do { id = *(volatile int*)&s_idx[s]; } while (id < 0);
            if (act) dst[s] = src[id];
        }
    }

    __syncthreads();
    cluster_sync_all();   // no CTA exits while peers may still touch its smem
}

extern "C" void kernel_launch(void* const* d_in, const int* in_sizes, int n_in,
                              void* d_out, int out_size) {
    const float* xyz  = (const float*)d_in[0];   // [B,3,N] fp32
    const float* feat = (const float*)d_in[1];   // [B,C,N] fp32
    float* out = (float*)d_out;

    // 16-CTA clusters need the non-portable opt-in (idempotent; capture-safe).
    cudaFuncSetAttribute(fps_kernel,
                         cudaFuncAttributeNonPortableClusterSizeAllowed, 1);

    cudaLaunchConfig_t cfg = {};
    cfg.gridDim = dim3(B * CSIZE, 1, 1);
    cfg.blockDim = dim3(T, 1, 1);
    cfg.dynamicSmemBytes = 0;
    cfg.stream = 0;
    cudaLaunchAttribute attrs[1];
    attrs[0].id = cudaLaunchAttributeClusterDimension;
    attrs[0].val.clusterDim.x = CSIZE;
    attrs[0].val.clusterDim.y = 1;
    attrs[0].val.clusterDim.z = 1;
    cfg.attrs = attrs;
    cfg.numAttrs = 1;
    cudaLaunchKernelEx(&cfg, fps_kernel, xyz, feat, out);
}

// round 16
// speedup vs baseline: 1.0608x; 1.0608x over previous
#include <cuda_runtime.h>
#include <cstdint>

#define B 8
#define N 32768
#define K 1024
#define C 128
#define CSIZE 16                 // CTAs per cluster (one cluster per batch)
#define T 128                    // threads per CTA
#define NW 4                     // warps per CTA
#define PPT 16                   // points per thread
#define NPAIR 8                  // f32x2 pairs per thread
#define SLOTS (CSIZE * NW)       // 64 warp-winner slots per CTA
#define TXK (SLOTS * 8)          // key barrier: 64 x 1 st.async.b64 = 512 B
#define TXC (SLOTS * 16)         // coord barrier: 64 x 2 st.async.b64 = 1024 B
#define FULL 0xffffffffu

typedef unsigned long long u64;

// FPS-selected indices, [B][K]
__device__ int g_fps_idx[B * K];

// ---------------- PTX helpers ----------------
__device__ __forceinline__ unsigned smem_u32(const void* p) {
    return (unsigned)__cvta_generic_to_shared(p);
}
__device__ __forceinline__ unsigned mapa_u32(unsigned addr, unsigned rank) {
    unsigned r;
    asm("mapa.shared::cluster.u32 %0, %1, %2;" : "=r"(r) : "r"(addr), "r"(rank));
    return r;
}
__device__ __forceinline__ u64 pk2f(float lo, float hi) {
    u64 v; asm("mov.b64 %0, {%1, %2};" : "=l"(v) : "f"(lo), "f"(hi)); return v;
}
__device__ __forceinline__ void upk2f(float& lo, float& hi, u64 v) {
    asm("mov.b64 {%0, %1}, %2;" : "=f"(lo), "=f"(hi) : "l"(v));
}
__device__ __forceinline__ u64 addx2(u64 a, u64 b) {
    u64 r; asm("add.rn.f32x2 %0, %1, %2;" : "=l"(r) : "l"(a), "l"(b)); return r;
}
__device__ __forceinline__ u64 subx2(u64 a, u64 b) {
    u64 r; asm("sub.rn.f32x2 %0, %1, %2;" : "=l"(r) : "l"(a), "l"(b)); return r;
}
__device__ __forceinline__ u64 mulx2(u64 a, u64 b) {
    u64 r; asm("mul.rn.f32x2 %0, %1, %2;" : "=l"(r) : "l"(a), "l"(b)); return r;
}
__device__ __forceinline__ void mbar_init(unsigned bar, unsigned cnt) {
    asm volatile("mbarrier.init.shared.b64 [%0], %1;" :: "r"(bar), "r"(cnt) : "memory");
}
// arrive(1) + raise expected tx: standard per-phase arming
__device__ __forceinline__ void mbar_expect(unsigned bar, unsigned tx) {
    asm volatile("mbarrier.arrive.expect_tx.shared.b64 _, [%0], %1;"
                 :: "r"(bar), "r"(tx) : "memory");
}
__device__ __forceinline__ void st_async64(unsigned raddr, u64 v, unsigned rbar) {
    asm volatile(
        "st.async.shared::cluster.mbarrier::complete_tx::bytes.b64 [%0], %1, [%2];"
        :: "r"(raddr), "l"(v), "r"(rbar) : "memory");
}
__device__ __forceinline__ void mbar_wait(unsigned bar, unsigned ph) {
    asm volatile(
        "{\n\t"
        ".reg .pred P;\n\t"
        "WL_%=:\n\t"
        "mbarrier.try_wait.parity.acquire.cluster.shared::cta.b64 P, [%0], %1, 0x989680;\n\t"
        "@P bra WD_%=;\n\t"
        "bra WL_%=;\n\t"
        "WD_%=:\n\t"
        "}"
        :: "r"(bar), "r"(ph) : "memory");
}
__device__ __forceinline__ u64 ld_smem64(unsigned addr) {
    u64 v;
    asm volatile("ld.shared.b64 %0, [%1];" : "=l"(v) : "r"(addr) : "memory");
    return v;
}
__device__ __forceinline__ void cluster_sync_all() {
    asm volatile("barrier.cluster.arrive.aligned;" ::: "memory");
    asm volatile("barrier.cluster.wait.aligned;" ::: "memory");
}
// 8-way u64 select by 3-bit p
__device__ __forceinline__ u64 sel8(const u64* A, int p) {
    u64 a0 = (p & 1) ? A[1] : A[0];
    u64 a1 = (p & 1) ? A[3] : A[2];
    u64 a2 = (p & 1) ? A[5] : A[4];
    u64 a3 = (p & 1) ? A[7] : A[6];
    u64 b0 = (p & 2) ? a1 : a0;
    u64 b1 = (p & 2) ? a3 : a2;
    return (p & 4) ? b1 : b0;
}

__global__ void __launch_bounds__(T, 1)
fps_kernel(const float* __restrict__ xyz) {
    // double-buffered exchange: packed (d,~idx) keys + coords
    __shared__ u64 s_di[2][SLOTS];   // (d<<32) | (~idx & 0x7fff)
    __shared__ u64 s_xy[2][SLOTS];   // packed (x, y)
    __shared__ u64 s_z[2][SLOTS];    // z bits in low 32
    __shared__ u64 s_kbar[2];        // key barriers  (gate the scan)
    __shared__ u64 s_cbar[2];        // coord barriers (waited after the scan)

    const int t = threadIdx.x;
    const int lane = t & 31;
    const int w = t >> 5;
    const int blk = blockIdx.x;
    const int b = blk / CSIZE;       // batch (clusters contiguous in x)
    const int r = blk % CSIZE;       // cluster rank

    const float* xb = xyz + (size_t)b * 3 * N;

    // Register-resident packed point slice + running scalar min-dist
    u64 PX[NPAIR], PY[NPAIR], PZ[NPAIR];
    float pd[PPT];
    const int base = r * (N / CSIZE) + t;
#pragma unroll
    for (int p = 0; p < NPAIR; p++) {
        PX[p] = pk2f(xb[base + (2 * p) * T],         xb[base + (2 * p + 1) * T]);
        PY[p] = pk2f(xb[N + base + (2 * p) * T],     xb[N + base + (2 * p + 1) * T]);
        PZ[p] = pk2f(xb[2 * N + base + (2 * p) * T], xb[2 * N + base + (2 * p + 1) * T]);
    }
#pragma unroll
    for (int j = 0; j < PPT; j++) pd[j] = __int_as_float(0x7f800000);  // +inf

    const unsigned kbar0 = smem_u32(&s_kbar[0]);
    const unsigned kbar1 = smem_u32(&s_kbar[1]);
    const unsigned cbar0 = smem_u32(&s_cbar[0]);
    const unsigned cbar1 = smem_u32(&s_cbar[1]);
    if (t == 0) {
        mbar_init(kbar0, 1); mbar_init(kbar1, 1);
        mbar_init(cbar0, 1); mbar_init(cbar1, 1);
    }
    __syncthreads();
    // Arm all first phases BEFORE any remote can complete_tx
    // (remotes st.async only after cluster_sync below).
    if (t == 0) {
        mbar_expect(kbar0, TXK); mbar_expect(kbar1, TXK);
        mbar_expect(cbar0, TXC); mbar_expect(cbar1, TXC);
    }

    // Hoisted DSMEM destination addresses. Rotation spreads fabric load.
    unsigned ra_di[2], ra_xy[2], ra_z[2], rkb[2], rcb[2];
    {
        const int slot = r * NW + w;
        const unsigned q = (unsigned)((lane + r) & 15);
        ra_di[0] = mapa_u32(smem_u32(&s_di[0][slot]), q);
        ra_di[1] = mapa_u32(smem_u32(&s_di[1][slot]), q);
        ra_xy[0] = mapa_u32(smem_u32(&s_xy[0][slot]), q);
        ra_xy[1] = mapa_u32(smem_u32(&s_xy[1][slot]), q);
        ra_z[0]  = mapa_u32(smem_u32(&s_z[0][slot]),  q);
        ra_z[1]  = mapa_u32(smem_u32(&s_z[1][slot]),  q);
        rkb[0]   = mapa_u32(kbar0, q);
        rkb[1]   = mapa_u32(kbar1, q);
        rcb[0]   = mapa_u32(cbar0, q);
        rcb[1]   = mapa_u32(cbar1, q);
    }
    // local scan addresses (this lane owns slots lane and lane+32)
    const unsigned pa0[2] = { smem_u32(&s_di[0][lane]), smem_u32(&s_di[1][lane]) };
    const unsigned pa1[2] = { smem_u32(&s_di[0][lane + 32]), smem_u32(&s_di[1][lane + 32]) };

    cluster_sync_all();

    int cur = 0;
    float cx = xb[0], cy = xb[N], cz = xb[2 * N];
    if (r == 0 && t == 0) g_fps_idx[b * K] = 0;

    for (int s = 0; s < K; s++) {
        // ---- packed distance update + thread-local argmax (exact .rn mul/add) ----
        const u64 ccx = pk2f(cx, cx);
        const u64 ccy = pk2f(cy, cy);
        const u64 ccz = pk2f(cz, cz);
        unsigned bestd = 0; int bestj = 0;
#pragma unroll
        for (int p = 0; p < NPAIR; p++) {
            u64 dx = subx2(PX[p], ccx);
            u64 dy = subx2(PY[p], ccy);
            u64 dz = subx2(PZ[p], ccz);
            u64 d2 = addx2(addx2(mulx2(dx, dx), mulx2(dy, dy)), mulx2(dz, dz));
            float da, db; upk2f(da, db, d2);
            float n0 = fminf(pd[2 * p], da);     pd[2 * p] = n0;
            unsigned u0 = __float_as_uint(n0);
            if (u0 > bestd) { bestd = u0; bestj = 2 * p; }       // strict > -> min idx
            float n1 = fminf(pd[2 * p + 1], db); pd[2 * p + 1] = n1;
            unsigned u1 = __float_as_uint(n1);
            if (u1 > bestd) { bestd = u1; bestj = 2 * p + 1; }
        }
        const unsigned besti = (unsigned)(base + (bestj << 7));   // bestj * T

        // ---- warp reduce: max dist, tie-break min idx ----
        const unsigned wm = __reduce_max_sync(FULL, bestd);
        const unsigned cand = (bestd == wm) ? ((besti << 5) | (unsigned)lane) : FULL;
        const unsigned cm = __reduce_min_sync(FULL, cand);
        const int sr = (int)(cm & 31);
        const unsigned wi = cm >> 5;

        const int par = s & 1;
        const unsigned ph = (unsigned)((s >> 1) & 1);
        const unsigned kbarp = par ? kbar1 : kbar0;
        const unsigned cbarp = par ? cbar1 : cbar0;

        // ---- send packed key IMMEDIATELY (completes on the KEY barrier only) ----
        if (lane < CSIZE) {
            const u64 key = ((u64)wm << 32) | (u64)((wi ^ 0x7fffu) & 0x7fffu);
            st_async64(ra_di[par], key, rkb[par]);
        }

        // ---- coords resolved + broadcast + sent (complete on the COORD barrier) ----
        {
            const int pp = bestj >> 1;
            float xl, xh, yl, yh, zl, zh;
            upk2f(xl, xh, sel8(PX, pp));
            upk2f(yl, yh, sel8(PY, pp));
            upk2f(zl, zh, sel8(PZ, pp));
            const bool hi = bestj & 1;
            float bx = hi ? xh : xl;
            float by = hi ? yh : yl;
            float bz = hi ? zh : zl;
            bx = __shfl_sync(FULL, bx, sr);
            by = __shfl_sync(FULL, by, sr);
            bz = __shfl_sync(FULL, bz, sr);
            if (lane < CSIZE) {
                st_async64(ra_xy[par], pk2f(bx, by), rcb[par]);
                st_async64(ra_z[par],  (u64)__float_as_uint(bz), rcb[par]);
            }
        }

        // ---- wait KEYS only (64 completions, no coord tail) ----
        mbar_wait(kbarp, ph);

        // ---- warp-cooperative global winner over 64 packed keys ----
        const u64 k0 = ld_smem64(pa0[par]);
        const u64 k1 = ld_smem64(pa1[par]);
        const bool take1 = k1 > k0;              // (max d, min idx) in one compare
        const u64 km = take1 ? k1 : k0;
        const unsigned dl = (unsigned)(km >> 32);
        const unsigned lo15 = (unsigned)km & 0x7fffu;        // ~idx
        const unsigned sl = (unsigned)lane + (take1 ? 32u : 0u);

        const unsigned gm = __reduce_max_sync(FULL, dl);
        const unsigned c2 = (dl == gm) ? ((lo15 << 6) | sl) : 0u;  // ~idx(15)<<6|slot
        const unsigned cm2 = __reduce_max_sync(FULL, c2);    // max ~idx = min idx
        const int slotw = (int)(cm2 & 63);
        cur = (int)(((cm2 >> 6) ^ 0x7fffu) & 0x7fffu);

        // ---- now wait coords (usually already complete -> fast path) ----
        mbar_wait(cbarp, ph);

        float fx, fy;
        upk2f(fx, fy, ld_smem64(smem_u32(&s_xy[par][slotw])));
        cx = fx; cy = fy;
        cz = __uint_as_float((unsigned)ld_smem64(smem_u32(&s_z[par][slotw])));

        // ---- deferred bookkeeping: shadowed under the next dist loop.
        // Re-arms are safe here: remote s+2 sends into buffer `par` causally
        // require my t0's s+1 key, which follows these re-arms in t0's
        // program order (message-chain transitivity, as in r9).
        if (t == 0) {
            mbar_expect(kbarp, TXK);
            mbar_expect(cbarp, TXC);
            if (r == 0 && s + 1 < K) g_fps_idx[b * K + s + 1] = cur;
        }
    }
    cluster_sync_all();   // no CTA exits while peers may still touch its smem
}

// out = [node_static (B,3,K)] ++ [node_feature (B,C,K)], row-major, fp32
__global__ void __launch_bounds__(K)
gather_kernel(const float* __restrict__ xyz, const float* __restrict__ feat,
              float* __restrict__ out) {
    const int b = blockIdx.y;
    const int e = blockIdx.x;   // 0..2 -> xyz, 3..130 -> feature channel e-3
    const int k = threadIdx.x;
    const int id = g_fps_idx[b * K + k];
    if (e < 3) {
        out[((size_t)(b * 3 + e)) * K + k] =
            xyz[(size_t)b * 3 * N + (size_t)e * N + id];
    } else {
        const int c = e - 3;
        out[(size_t)B * 3 * K + ((size_t)(b * C + c)) * K + k] =
            feat[(size_t)b * C * N + (size_t)c * N + id];
    }
}

extern "C" void kernel_launch(void* const* d_in, const int* in_sizes, int n_in,
                              void* d_out, int out_size) {
    const float* xyz  = (const float*)d_in[0];   // [B,3,N] fp32
    const float* feat = (const float*)d_in[1];   // [B,C,N] fp32
    float* out = (float*)d_out;

    // 16-CTA clusters need the non-portable opt-in (idempotent; capture-safe).
    cudaFuncSetAttribute(fps_kernel,
                         cudaFuncAttributeNonPortableClusterSizeAllowed, 1);

    cudaLaunchConfig_t cfg = {};
    cfg.gridDim = dim3(B * CSIZE, 1, 1);
    cfg.blockDim = dim3(T, 1, 1);
    cfg.dynamicSmemBytes = 0;
    cfg.stream = 0;
    cudaLaunchAttribute attrs[1];
    attrs[0].id = cudaLaunchAttributeClusterDimension;
    attrs[0].val.clusterDim.x = CSIZE;
    attrs[0].val.clusterDim.y = 1;
    attrs[0].val.clusterDim.z = 1;
    cfg.attrs = attrs;
    cfg.numAttrs = 1;
    cudaLaunchKernelEx(&cfg, fps_kernel, xyz);

    gather_kernel<<<dim3(3 + C, B), K>>>(xyz, feat, out);
}

// round 17
// speedup vs baseline: 1.0916x; 1.0290x over previous
#include <cuda_runtime.h>
#include <cstdint>

#define B 8
#define N 32768
#define K 1024
#define C 128
#define CSIZE 16                 // CTAs per cluster (one cluster per batch)
#define T 128                    // threads per CTA
#define NW 4                     // warps per CTA
#define PPT 16                   // points per thread
#define NPAIR 8                  // f32x2 pairs per thread
#define SLOTS (CSIZE * NW)       // 64 warp-winner slots per CTA
#define TXK (SLOTS * 8)          // key barrier: 64 x 1 st.async.b64 = 512 B
#define TXC (SLOTS * 16)         // coord barrier: 64 x 2 st.async.b64 = 1024 B
#define FULL 0xffffffffu

typedef unsigned long long u64;

// FPS-selected indices, [B][K]
__device__ int g_fps_idx[B * K];

// ---------------- PTX helpers ----------------
__device__ __forceinline__ unsigned smem_u32(const void* p) {
    return (unsigned)__cvta_generic_to_shared(p);
}
__device__ __forceinline__ unsigned mapa_u32(unsigned addr, unsigned rank) {
    unsigned r;
    asm("mapa.shared::cluster.u32 %0, %1, %2;" : "=r"(r) : "r"(addr), "r"(rank));
    return r;
}
__device__ __forceinline__ u64 pk2f(float lo, float hi) {
    u64 v; asm("mov.b64 %0, {%1, %2};" : "=l"(v) : "f"(lo), "f"(hi)); return v;
}
__device__ __forceinline__ void upk2f(float& lo, float& hi, u64 v) {
    asm("mov.b64 {%0, %1}, %2;" : "=f"(lo), "=f"(hi) : "l"(v));
}
__device__ __forceinline__ u64 addx2(u64 a, u64 b) {
    u64 r; asm("add.rn.f32x2 %0, %1, %2;" : "=l"(r) : "l"(a), "l"(b)); return r;
}
__device__ __forceinline__ u64 subx2(u64 a, u64 b) {
    u64 r; asm("sub.rn.f32x2 %0, %1, %2;" : "=l"(r) : "l"(a), "l"(b)); return r;
}
__device__ __forceinline__ u64 mulx2(u64 a, u64 b) {
    u64 r; asm("mul.rn.f32x2 %0, %1, %2;" : "=l"(r) : "l"(a), "l"(b)); return r;
}
__device__ __forceinline__ void mbar_init(unsigned bar, unsigned cnt) {
    asm volatile("mbarrier.init.shared.b64 [%0], %1;" :: "r"(bar), "r"(cnt) : "memory");
}
// arrive (count 1) + raise expected tx: standard per-phase arming
__device__ __forceinline__ void mbar_expect(unsigned bar, unsigned tx) {
    asm volatile("mbarrier.arrive.expect_tx.shared.b64 _, [%0], %1;"
                 :: "r"(bar), "r"(tx) : "memory");
}
__device__ __forceinline__ void st_async64(unsigned raddr, u64 v, unsigned rbar) {
    asm volatile(
        "st.async.shared::cluster.mbarrier::complete_tx::bytes.b64 [%0], %1, [%2];"
        :: "r"(raddr), "l"(v), "r"(rbar) : "memory");
}
__device__ __forceinline__ void mbar_wait(unsigned bar, unsigned ph) {
    asm volatile(
        "{\n\t"
        ".reg .pred P;\n\t"
        "WL_%=:\n\t"
        "mbarrier.try_wait.parity.acquire.cluster.shared::cta.b64 P, [%0], %1, 0x989680;\n\t"
        "@P bra WD_%=;\n\t"
        "bra WL_%=;\n\t"
        "WD_%=:\n\t"
        "}"
        :: "r"(bar), "r"(ph) : "memory");
}
__device__ __forceinline__ u64 ld_smem64(unsigned addr) {
    u64 v;
    asm volatile("ld.shared.b64 %0, [%1];" : "=l"(v) : "r"(addr) : "memory");
    return v;
}
__device__ __forceinline__ void cluster_sync_all() {
    asm volatile("barrier.cluster.arrive.aligned;" ::: "memory");
    asm volatile("barrier.cluster.wait.aligned;" ::: "memory");
}
// 8-way u64 select by 3-bit p
__device__ __forceinline__ u64 sel8(const u64* A, int p) {
    u64 a0 = (p & 1) ? A[1] : A[0];
    u64 a1 = (p & 1) ? A[3] : A[2];
    u64 a2 = (p & 1) ? A[5] : A[4];
    u64 a3 = (p & 1) ? A[7] : A[6];
    u64 b0 = (p & 2) ? a1 : a0;
    u64 b1 = (p & 2) ? a3 : a2;
    return (p & 4) ? b1 : b0;
}

__global__ void __launch_bounds__(T, 1)
fps_kernel(const float* __restrict__ xyz) {
    // double-buffered exchange: packed (d,~idx) keys + coords
    __shared__ u64 s_di[2][SLOTS];   // (d<<32) | (~idx & 0x7fff)
    __shared__ u64 s_xy[2][SLOTS];   // packed (x, y)
    __shared__ u64 s_z[2][SLOTS];    // z bits in low 32
    __shared__ u64 s_kbar[2];        // key barrier  (gates the scan)
    __shared__ u64 s_cbar[2];        // coord barrier (waited after the scan)

    const int t = threadIdx.x;
    const int lane = t & 31;
    const int w = t >> 5;
    const int blk = blockIdx.x;
    const int b = blk / CSIZE;       // batch (clusters contiguous in x)
    const int r = blk % CSIZE;       // cluster rank

    const float* xb = xyz + (size_t)b * 3 * N;

    // Register-resident packed point slice + running scalar min-dist
    u64 PX[NPAIR], PY[NPAIR], PZ[NPAIR];
    float pd[PPT];
    const int base = r * (N / CSIZE) + t;
#pragma unroll
    for (int p = 0; p < NPAIR; p++) {
        PX[p] = pk2f(xb[base + (2 * p) * T],         xb[base + (2 * p + 1) * T]);
        PY[p] = pk2f(xb[N + base + (2 * p) * T],     xb[N + base + (2 * p + 1) * T]);
        PZ[p] = pk2f(xb[2 * N + base + (2 * p) * T], xb[2 * N + base + (2 * p + 1) * T]);
    }
#pragma unroll
    for (int j = 0; j < PPT; j++) pd[j] = __int_as_float(0x7f800000);  // +inf

    const unsigned kbar0 = smem_u32(&s_kbar[0]);
    const unsigned kbar1 = smem_u32(&s_kbar[1]);
    const unsigned cbar0 = smem_u32(&s_cbar[0]);
    const unsigned cbar1 = smem_u32(&s_cbar[1]);
    if (t == 0) {
        mbar_init(kbar0, 1); mbar_init(kbar1, 1);
        mbar_init(cbar0, 1); mbar_init(cbar1, 1);
    }
    __syncthreads();
    // Arm all first phases BEFORE any remote can complete_tx
    // (remotes st.async only after cluster_sync below).
    if (t == 0) {
        mbar_expect(kbar0, TXK); mbar_expect(kbar1, TXK);
        mbar_expect(cbar0, TXC); mbar_expect(cbar1, TXC);
    }

    // Hoisted DSMEM destination addresses. Rotation spreads fabric load.
    unsigned ra_di[2], ra_xy[2], ra_z[2], rkb[2], rcb[2];
    {
        const int slot = r * NW + w;
        const unsigned q = (unsigned)((lane + r) & 15);
        ra_di[0] = mapa_u32(smem_u32(&s_di[0][slot]), q);
        ra_di[1] = mapa_u32(smem_u32(&s_di[1][slot]), q);
        ra_xy[0] = mapa_u32(smem_u32(&s_xy[0][slot]), q);
        ra_xy[1] = mapa_u32(smem_u32(&s_xy[1][slot]), q);
        ra_z[0]  = mapa_u32(smem_u32(&s_z[0][slot]),  q);
        ra_z[1]  = mapa_u32(smem_u32(&s_z[1][slot]),  q);
        rkb[0]   = mapa_u32(kbar0, q);
        rkb[1]   = mapa_u32(kbar1, q);
        rcb[0]   = mapa_u32(cbar0, q);
        rcb[1]   = mapa_u32(cbar1, q);
    }
    // local scan addresses (this lane owns slots lane and lane+32)
    const unsigned pa0[2] = { smem_u32(&s_di[0][lane]), smem_u32(&s_di[1][lane]) };
    const unsigned pa1[2] = { smem_u32(&s_di[0][lane + 32]), smem_u32(&s_di[1][lane + 32]) };

    cluster_sync_all();

    int cur = 0;
    float cx = xb[0], cy = xb[N], cz = xb[2 * N];

    for (int s = 0; s < K; s++) {
        if (r == 0 && t == 0) g_fps_idx[b * K + s] = cur;

        // ---- packed distance update + thread-local argmax (exact .rn mul/add) ----
        const u64 ccx = pk2f(cx, cx);
        const u64 ccy = pk2f(cy, cy);
        const u64 ccz = pk2f(cz, cz);
        unsigned bestd = 0; int bestj = 0;
#pragma unroll
        for (int p = 0; p < NPAIR; p++) {
            u64 dx = subx2(PX[p], ccx);
            u64 dy = subx2(PY[p], ccy);
            u64 dz = subx2(PZ[p], ccz);
            u64 d2 = addx2(addx2(mulx2(dx, dx), mulx2(dy, dy)), mulx2(dz, dz));
            float da, db; upk2f(da, db, d2);
            float n0 = fminf(pd[2 * p], da);     pd[2 * p] = n0;
            unsigned u0 = __float_as_uint(n0);
            if (u0 > bestd) { bestd = u0; bestj = 2 * p; }       // strict > -> min idx
            float n1 = fminf(pd[2 * p + 1], db); pd[2 * p + 1] = n1;
            unsigned u1 = __float_as_uint(n1);
            if (u1 > bestd) { bestd = u1; bestj = 2 * p + 1; }
        }
        const unsigned besti = (unsigned)(base + (bestj << 7));   // bestj * T

        // ---- warp reduce: max dist, tie-break min idx ----
        const unsigned wm = __reduce_max_sync(FULL, bestd);
        const unsigned cand = (bestd == wm) ? ((besti << 5) | (unsigned)lane) : FULL;
        const unsigned cm = __reduce_min_sync(FULL, cand);
        const int sr = (int)(cm & 31);
        const unsigned wi = cm >> 5;

        const int par = s & 1;
        const unsigned ph = (unsigned)((s >> 1) & 1);
        const unsigned kbarp = par ? kbar1 : kbar0;
        const unsigned cbarp = par ? cbar1 : cbar0;

        // ---- send packed key IMMEDIATELY (completes on the KEY barrier only) ----
        if (lane < CSIZE) {
            const u64 key = ((u64)wm << 32) | (u64)((wi ^ 0x7fffu) & 0x7fffu);
            st_async64(ra_di[par], key, rkb[par]);
        }

        // ---- coords resolved + broadcast + sent (complete on the COORD barrier) ----
        {
            const int pp = bestj >> 1;
            float xl, xh, yl, yh, zl, zh;
            upk2f(xl, xh, sel8(PX, pp));
            upk2f(yl, yh, sel8(PY, pp));
            upk2f(zl, zh, sel8(PZ, pp));
            const bool hi = bestj & 1;
            float bx = hi ? xh : xl;
            float by = hi ? yh : yl;
            float bz = hi ? zh : zl;
            bx = __shfl_sync(FULL, bx, sr);
            by = __shfl_sync(FULL, by, sr);
            bz = __shfl_sync(FULL, bz, sr);
            if (lane < CSIZE) {
                st_async64(ra_xy[par], pk2f(bx, by), rcb[par]);
                st_async64(ra_z[par],  (u64)__float_as_uint(bz), rcb[par]);
            }
        }

        // ---- wait KEYS only (64 completions, no coord tail); re-arm for s+2 ----
        mbar_wait(kbarp, ph);
        if (t == 0) mbar_expect(kbarp, TXK);

        // ---- warp-cooperative global winner over 64 packed keys ----
        const u64 k0 = ld_smem64(pa0[par]);
        const u64 k1 = ld_smem64(pa1[par]);
        const bool take1 = k1 > k0;              // (max d, min idx) in one compare
        const u64 km = take1 ? k1 : k0;
        const unsigned dl = (unsigned)(km >> 32);
        const unsigned lo15 = (unsigned)km & 0x7fffu;        // ~idx
        const unsigned sl = (unsigned)lane + (take1 ? 32u : 0u);

        const unsigned gm = __reduce_max_sync(FULL, dl);
        const unsigned c2 = (dl == gm) ? ((lo15 << 6) | sl) : 0u;  // ~idx(15)<<6|slot
        const unsigned cm2 = __reduce_max_sync(FULL, c2);    // max ~idx = min idx
        const int slotw = (int)(cm2 & 63);
        cur = (int)(((cm2 >> 6) ^ 0x7fffu) & 0x7fffu);

        // ---- now wait coords (usually already complete -> fast path) ----
        mbar_wait(cbarp, ph);
        if (t == 0) mbar_expect(cbarp, TXC);

        float fx, fy;
        upk2f(fx, fy, ld_smem64(smem_u32(&s_xy[par][slotw])));
        cx = fx; cy = fy;
        cz = __uint_as_float((unsigned)ld_smem64(smem_u32(&s_z[par][slotw])));
    }
    cluster_sync_all();   // no CTA exits while peers may still touch its smem
}

// out = [node_static (B,3,K)] ++ [node_feature (B,C,K)], row-major, fp32
__global__ void __launch_bounds__(K)
gather_kernel(const float* __restrict__ xyz, const float* __restrict__ feat,
              float* __restrict__ out) {
    const int b = blockIdx.y;
    const int e = blockIdx.x;   // 0..2 -> xyz, 3..130 -> feature channel e-3
    const int k = threadIdx.x;
    const int id = g_fps_idx[b * K + k];
    if (e < 3) {
        out[((size_t)(b * 3 + e)) * K + k] =
            xyz[(size_t)b * 3 * N + (size_t)e * N + id];
    } else {
        const int c = e - 3;
        out[(size_t)B * 3 * K + ((size_t)(b * C + c)) * K + k] =
            feat[(size_t)b * C * N + (size_t)c * N + id];
    }
}

extern "C" void kernel_launch(void* const* d_in, const int* in_sizes, int n_in,
                              void* d_out, int out_size) {
    const float* xyz  = (const float*)d_in[0];   // [B,3,N] fp32
    const float* feat = (const float*)d_in[1];   // [B,C,N] fp32
    float* out = (float*)d_out;

    // 16-CTA clusters need the non-portable opt-in (idempotent; capture-safe).
    cudaFuncSetAttribute(fps_kernel,
                         cudaFuncAttributeNonPortableClusterSizeAllowed, 1);

    cudaLaunchConfig_t cfg = {};
    cfg.gridDim = dim3(B * CSIZE, 1, 1);
    cfg.blockDim = dim3(T, 1, 1);
    cfg.dynamicSmemBytes = 0;
    cfg.stream = 0;
    cudaLaunchAttribute attrs[1];
    attrs[0].id = cudaLaunchAttributeClusterDimension;
    attrs[0].val.clusterDim.x = CSIZE;
    attrs[0].val.clusterDim.y = 1;
    attrs[0].val.clusterDim.z = 1;
    cfg.attrs = attrs;
    cfg.numAttrs = 1;
    cudaLaunchKernelEx(&cfg, fps_kernel, xyz);

    gather_kernel<<<dim3(3 + C, B), K>>>(xyz, feat, out);
}